// round 8
// baseline (speedup 1.0000x reference)
#include <cuda_runtime.h>
#include <math.h>

#define Hd 512
#define Wd 512
#define NPTS 2048           // 64 segments * 32 samples
#define NT 512
#define RPB 4               // rows per block
#define GRID (Hd / RPB)     // 128 blocks = one wave on 148 SMs
#define RADIUS 12.0f        // sigma(-12) = 6.1e-6 truncation
#define NBIN 16             // 32-pixel bins, one per warp
#define CAP 96              // per-(row,bin) capacity
#define WCAP 2048           // worklist capacity (expected ~640)

struct Smem {
    float2 bin[RPB][NBIN][CAP];   // 48 KB
    int    cnt[RPB][NBIN];
    float  carry[RPB][Wd + 1];    // 8.2 KB
    float  wxc[WCAP];             // worklist: x-crossing
    float  wt[WCAP];              //           t (full precision)
    int    wmeta[WCAP];           //           rr | sign<<8
    float  wsum[16];
    int    nwork;
};

__device__ __forceinline__ float fsig(float z) {
    return __fdividef(1.0f, 1.0f + __expf(-z));
}

__device__ __forceinline__ float2 bez(const float2* c2, int idx) {
    int seg = idx >> 5;
    int k   = idx & 31;
    float t  = (float)k * (1.0f / 31.0f);
    float mt = 1.0f - t;
    float2 p0 = c2[3 * seg + 0];
    float2 p1 = c2[3 * seg + 1];
    float2 p2 = c2[3 * seg + 2];
    float2 p3 = c2[3 * seg + 3];
    float w0 = mt * mt * mt;
    float w1 = 3.0f * mt * mt * t;
    float w2 = 3.0f * mt * t * t;
    float w3 = t * t * t;
    return make_float2(w0 * p0.x + w1 * p1.x + w2 * p2.x + w3 * p3.x,
                       w0 * p0.y + w1 * p1.y + w2 * p2.y + w3 * p3.y);
}

__global__ __launch_bounds__(NT)
void render4(const float* __restrict__ cp,
             const float* __restrict__ color,
             float* __restrict__ out) {
    extern __shared__ char smem_raw[];
    Smem* S = (Smem*)smem_raw;

    const int tid  = threadIdx.x;
    const int lane = tid & 31;
    const int wp   = tid >> 5;
    const int y0   = blockIdx.x * RPB;
    const float2* c2 = (const float2*)cp;

    // --- zero accumulators ---
    for (int i = tid; i < RPB * (Wd + 1); i += NT) ((float*)S->carry)[i] = 0.0f;
    if (tid < RPB * NBIN) ((int*)S->cnt)[tid] = 0;
    if (tid == 0) S->nwork = 0;
    __syncthreads();

    // --- Stage 1: thread owns edges 4t..4t+3 (5 shared sample points) ---
    {
        float2 p[5];
        #pragma unroll
        for (int k = 0; k < 5; ++k) p[k] = bez(c2, (4 * tid + k) & (NPTS - 1));
        #pragma unroll
        for (int j = 0; j < 4; ++j) {
            float2 a = p[j], b = p[j + 1];
            float dy = b.y - a.y;
            if (fabsf(dy) < 1e-6f) continue;          // reference mask==0
            float dyp   = dy + 1e-8f;
            float invdy = __fdividef(1.0f, dyp);
            float dx    = b.x - a.x;
            int   sgn   = (dyp > 0.0f) ? 0x100 : 0;
            #pragma unroll
            for (int rr = 0; rr < RPB; ++rr) {
                float t = ((float)(y0 + rr) - a.y) * invdy;
                if (t >= -1.0f && t <= 2.0f) {        // sig(20)=2e-9 beyond band
                    int q = atomicAdd(&S->nwork, 1);
                    if (q < WCAP) {
                        S->wxc[q]   = fmaf(t, dx, a.x);
                        S->wt[q]    = t;
                        S->wmeta[q] = rr | sgn;
                    }
                }
            }
        }
    }
    __syncthreads();

    // --- Stage 2: drain worklist with full lanes (the 2-sigma weight math) ---
    {
        int nw = min(S->nwork, WCAP);
        for (int i = tid; i < nw; i += NT) {
            float t    = S->wt[i];
            float xc   = S->wxc[i];
            int   meta = S->wmeta[i];
            int   rr   = meta & 0xff;
            float w = fsig(20.0f * t) * fsig(20.0f - 20.0f * t);
            w = (meta & 0x100) ? w : -w;              // sign(dy)

            int ci = min(max((int)ceilf(xc - RADIUS), 0), Wd);
            atomicAdd(&S->carry[rr][ci], w);          // full weight for x < ci

            int b0 = max((int)floorf((xc - RADIUS) * (1.0f / 32.0f)), 0);
            int b1 = min((int)floorf((xc + RADIUS) * (1.0f / 32.0f)), NBIN - 1);
            for (int b = b0; b <= b1; ++b) {
                int q = atomicAdd(&S->cnt[rr][b], 1);
                if (q < CAP) S->bin[rr][b][q] = make_float2(xc, w);
            }
        }
    }
    __syncthreads();

    // --- Phase B: thread owns pixel x=tid; warp scans its own bin, 4 rows ---
    float wind[RPB] = {0.0f, 0.0f, 0.0f, 0.0f};
    {
        const float fx = (float)tid;
        #pragma unroll
        for (int rr = 0; rr < RPB; ++rr) {
            int m = min(S->cnt[rr][wp], CAP);
            for (int i = 0; i < m; ++i) {
                float2 E = S->bin[rr][wp][i];         // broadcast LDS
                float z = E.x - fx;
                if (fabsf(z) <= RADIUS)
                    wind[rr] += E.y * fsig(z);        // x>=ci <=> z<=R
            }
        }
    }
    __syncthreads();

    // --- 4 suffix scans: P[tid] = sum_{j >= 512-tid} carry[rr][j] ---
    #pragma unroll
    for (int rr = 0; rr < RPB; ++rr) {
        float v = S->carry[rr][Wd - tid];
        __syncthreads();
        float val = v;
        #pragma unroll
        for (int o = 1; o < 32; o <<= 1) {
            float nb = __shfl_up_sync(0xffffffffu, val, o);
            if (lane >= o) val += nb;
        }
        if (lane == 31) S->wsum[wp] = val;
        __syncthreads();
        if (wp == 0) {
            float s = (lane < 16) ? S->wsum[lane] : 0.0f;
            #pragma unroll
            for (int o = 1; o < 16; o <<= 1) {
                float nb = __shfl_up_sync(0xffffffffu, s, o);
                if (lane >= o) s += nb;
            }
            if (lane < 16) S->wsum[lane] = s;
        }
        __syncthreads();
        if (wp > 0) val += S->wsum[wp - 1];
        S->carry[rr][tid] = val;                      // P[tid]
        __syncthreads();
    }

    // --- output: wind += P[511-x]; alpha = sigmoid(4*wind) ---
    float cr = __ldg(&color[0]), cg = __ldg(&color[1]), cb = __ldg(&color[2]);
    #pragma unroll
    for (int rr = 0; rr < RPB; ++rr) {
        float w = wind[rr] + S->carry[rr][(Wd - 1) - tid];
        float alpha = fsig(4.0f * w);
        ((float4*)out)[(y0 + rr) * Wd + tid] = make_float4(cr, cg, cb, alpha);
    }
}

extern "C" void kernel_launch(void* const* d_in, const int* in_sizes, int n_in,
                              void* d_out, int out_size) {
    (void)in_sizes; (void)n_in; (void)out_size;
    const float* cp    = (const float*)d_in[0];   // (193,2) float32
    const float* color = (const float*)d_in[1];   // (3,)    float32
    float* out = (float*)d_out;                   // (512,512,4) float32
    size_t sh = sizeof(Smem);                     // ~82 KB dynamic smem
    cudaFuncSetAttribute(render4, cudaFuncAttributeMaxDynamicSharedMemorySize, (int)sh);
    render4<<<GRID, NT, sh>>>(cp, color, out);
}

// round 9
// speedup vs baseline: 1.5736x; 1.5736x over previous
#include <cuda_runtime.h>
#include <math.h>

#define Hd 512
#define Wd 512
#define NPTS 2048           // 64 segments * 32 samples
#define NT 512
#define RADIUS 12.0f        // sigma(-12) = 6.1e-6 truncation
#define NBIN 16             // 32-pixel bins, one per warp
#define CAP 128             // per-bin capacity

__shared__ float2 s_bin[NBIN][CAP];   // 16 KB: (xc, w) per bin
__shared__ int    s_cnt[NBIN];
__shared__ float  s_wc[NBIN + 1];     // full-weight buckets: wc[b] -> warps < b
__shared__ float  s_wcs[NBIN];        // suffix sums: wcs[j] = sum_{b>j} wc[b]

__device__ __forceinline__ float fsig(float z) {
    return __fdividef(1.0f, 1.0f + __expf(-z));
}

__device__ __forceinline__ float2 bez(const float2* c2, int idx) {
    int seg = idx >> 5;
    int k   = idx & 31;
    float t  = (float)k * (1.0f / 31.0f);
    float mt = 1.0f - t;
    float2 p0 = c2[3 * seg + 0];
    float2 p1 = c2[3 * seg + 1];
    float2 p2 = c2[3 * seg + 2];
    float2 p3 = c2[3 * seg + 3];
    float w0 = mt * mt * mt;
    float w1 = 3.0f * mt * mt * t;
    float w2 = 3.0f * mt * t * t;
    float w3 = t * t * t;
    return make_float2(w0 * p0.x + w1 * p1.x + w2 * p2.x + w3 * p3.x,
                       w0 * p0.y + w1 * p1.y + w2 * p2.y + w3 * p3.y);
}

// One block per row. Warp w owns pixels [32w, 32w+31].
__global__ __launch_bounds__(NT)
void render_row(const float* __restrict__ cp,
                const float* __restrict__ color,
                float* __restrict__ out) {
    const int tid  = threadIdx.x;
    const int lane = tid & 31;
    const int wp   = tid >> 5;
    const int y    = blockIdx.x;
    const float gy = (float)y;
    const float2* c2 = (const float2*)cp;

    if (tid < NBIN) { s_cnt[tid] = 0; s_wc[tid] = 0.0f; }
    if (tid == 0) s_wc[NBIN] = 0.0f;
    __syncthreads();

    // --- Phase A: thread owns edges 4t..4t+3 (5 shared Bezier samples) ---
    {
        float2 p[5];
        #pragma unroll
        for (int k = 0; k < 5; ++k) p[k] = bez(c2, (4 * tid + k) & (NPTS - 1));
        #pragma unroll
        for (int j = 0; j < 4; ++j) {
            float2 a = p[j], b = p[j + 1];
            float dy = b.y - a.y;
            if (fabsf(dy) < 1e-6f) continue;            // reference mask==0
            float dyp = dy + 1e-8f;
            float t = (gy - a.y) * __fdividef(1.0f, dyp);
            if (!(t >= -1.0f && t <= 2.0f)) continue;   // sig(20)=2e-9 beyond
            float w = fsig(20.0f * t) * fsig(20.0f - 20.0f * t);
            w = (dyp > 0.0f) ? w : -w;                  // sign(dy)
            float xc = fmaf(t, b.x - a.x, a.x);

            int b0r = (int)floorf((xc - RADIUS) * (1.0f / 32.0f));
            int b1r = (int)floorf((xc + RADIUS) * (1.0f / 32.0f));
            if (b1r < 0) continue;                      // fully left: all zero
            if (b0r >= NBIN) {                          // fully right: all full
                atomicAdd(&s_wc[NBIN], w);
                continue;
            }
            if (b0r > 0) atomicAdd(&s_wc[b0r], w);      // warps < b0r get w
            int b0 = max(b0r, 0);
            int b1 = min(b1r, NBIN - 1);
            for (int bb = b0; bb <= b1; ++bb) {
                int q = atomicAdd(&s_cnt[bb], 1);
                if (q < CAP) s_bin[bb][q] = make_float2(xc, w);
            }
        }
    }
    __syncthreads();

    // --- warp 0: suffix-scan the 16 buckets while others start Phase B ---
    if (wp == 0 && lane < NBIN) {
        float v = s_wc[lane + 1];
        #pragma unroll
        for (int o = 1; o < NBIN; o <<= 1) {
            float nb = __shfl_down_sync(0x0000ffffu, v, o);
            if (lane + o < NBIN) v += nb;
        }
        s_wcs[lane] = v;            // wcs[j] = sum_{b > j} wc[b]
    }

    // --- Phase B: thread owns pixel x=tid; warp scans exactly its own bin ---
    float wind = 0.0f;
    {
        const float fx = (float)tid;
        int m = min(s_cnt[wp], CAP);
        for (int i = 0; i < m; ++i) {
            float2 E = s_bin[wp][i];                    // broadcast LDS
            float z = E.x - fx;
            if (z > RADIUS)        wind += E.y;         // full weight
            else if (z >= -RADIUS) wind += E.y * fsig(z);
        }
    }
    __syncthreads();

    // --- combine + output ---
    wind += s_wcs[wp];
    float alpha = fsig(4.0f * wind);
    float cr = __ldg(&color[0]), cg = __ldg(&color[1]), cb = __ldg(&color[2]);
    ((float4*)out)[y * Wd + tid] = make_float4(cr, cg, cb, alpha);
}

extern "C" void kernel_launch(void* const* d_in, const int* in_sizes, int n_in,
                              void* d_out, int out_size) {
    (void)in_sizes; (void)n_in; (void)out_size;
    const float* cp    = (const float*)d_in[0];   // (193,2) float32
    const float* color = (const float*)d_in[1];   // (3,)    float32
    float* out = (float*)d_out;                   // (512,512,4) float32
    render_row<<<Hd, NT>>>(cp, color, out);
}